// round 2
// baseline (speedup 1.0000x reference)
#include <cuda_runtime.h>
#include <math_constants.h>

#define BATCH 16
#define LEN   128
#define VOCAB 32128
#define EMB   768
#define V4    (VOCAB / 4)     // 8032
#define E4    (EMB / 4)       // 192
#define CH    8               // chunks per token
#define NTOK  (BATCH * LEN)   // 2048
#define NITEMS (NTOK * CH)    // 16384
#define CHUNK_V4 (V4 / CH)    // 1004 float4-pairs per item (32KB)
#define ABLK  256
#define AGRID (148 * 4)       // 592 persistent blocks
#define ANW   (ABLK / 32)     // 8

// persistent scratch (device globals are zero-initialized at module load;
// g_counter is reset by emit_kernel at the end of every launch)
__device__ unsigned int       g_counter;
__device__ unsigned long long g_best[NITEMS];

// Bit-exact replication of XLA f32:
//   linspace(-1,1,V)[h] = -1 + h*fl(2/(V-1));  ix = ((c+1)*V - 1)/2
//   round half-even, clip. Forced discrete IEEE ops (no FMA contraction).
__device__ __forceinline__ int row_from_hot(int h) {
    const float delta = 2.0f / 32127.0f;
    float coord = __fadd_rn(-1.0f, __fmul_rn((float)h, delta));
    float t = __fadd_rn(coord, 1.0f);
    t = __fmul_rn(t, 32128.0f);
    t = __fsub_rn(t, 1.0f);
    t = __fdiv_rn(t, 2.0f);
    float r = rintf(t);
    r = fminf(fmaxf(r, 0.0f), 32127.0f);
    return (int)r;
}

// monotone f32 -> u32 key (total order preserved)
__device__ __forceinline__ unsigned int fkey(float v) {
    unsigned int b = __float_as_uint(v);
    unsigned int m = (unsigned int)((int)b >> 31) | 0x80000000u;
    return b ^ m;
}

__global__ void __launch_bounds__(ABLK, 4)
argmax_kernel(const float* __restrict__ logits,
              const int*   __restrict__ mask,
              const float* __restrict__ gumbel)
{
    const int tid  = threadIdx.x;
    const int lane = tid & 31;
    const int wid  = tid >> 5;

    __shared__ float        s_wv[ANW];
    __shared__ int          s_wi[ANW];
    __shared__ unsigned int s_item;

    // first grab
    if (tid == 0) s_item = atomicAdd(&g_counter, 1u);
    __syncthreads();
    unsigned int item = s_item;
    __syncthreads();   // all threads have read s_item before it is rewritten

    while (item < NITEMS) {
        // prefetch next item (latency hidden under processing)
        if (tid == 0) s_item = atomicAdd(&g_counter, 1u);

        const int tok = (int)(item >> 3);        // CH == 8
        const int c   = (int)(item & (CH - 1));

        if (mask[tok] != 0) {
            const float4* lg = reinterpret_cast<const float4*>(logits) + (long)tok * V4;
            const float4* gn = reinterpret_cast<const float4*>(gumbel) + (long)tok * V4;
            const int i0  = c * CHUNK_V4;
            const int end = i0 + CHUNK_V4;

            float best = -CUDART_INF_F;
            int   bi   = 0x7fffffff;
            #pragma unroll 2
            for (int i = i0 + tid; i < end; i += ABLK) {
                float4 a = __ldg(lg + i);
                float4 g = __ldg(gn + i);
                float z0 = a.x + g.x, z1 = a.y + g.y, z2 = a.z + g.z, z3 = a.w + g.w;
                int base = i << 2;
                if (z0 > best) { best = z0; bi = base;     }
                if (z1 > best) { best = z1; bi = base + 1; }
                if (z2 > best) { best = z2; bi = base + 2; }
                if (z3 > best) { best = z3; bi = base + 3; }
            }
            // warp reduce: larger value wins; tie -> lower index
            #pragma unroll
            for (int off = 16; off > 0; off >>= 1) {
                float ov = __shfl_down_sync(0xffffffffu, best, off);
                int   oi = __shfl_down_sync(0xffffffffu, bi,   off);
                if (ov > best || (ov == best && oi < bi)) { best = ov; bi = oi; }
            }
            if (lane == 0) { s_wv[wid] = best; s_wi[wid] = bi; }
            __syncthreads();
            if (wid == 0) {
                best = (lane < ANW) ? s_wv[lane] : -CUDART_INF_F;
                bi   = (lane < ANW) ? s_wi[lane] : 0x7fffffff;
                #pragma unroll
                for (int off = 4; off > 0; off >>= 1) {
                    float ov = __shfl_down_sync(0xffffffffu, best, off);
                    int   oi = __shfl_down_sync(0xffffffffu, bi,   off);
                    if (ov > best || (ov == best && oi < bi)) { best = ov; bi = oi; }
                }
                if (lane == 0) {
                    unsigned long long packed =
                        ((unsigned long long)fkey(best) << 32) |
                        (unsigned long long)(0xFFFFFFFFu - (unsigned int)bi);
                    g_best[item] = packed;
                }
            }
        }

        __syncthreads();          // s_item ready, s_wv/s_wi safe to reuse
        item = s_item;
        __syncthreads();          // all read before next rewrite
    }
}

__global__ void __launch_bounds__(192)
emit_kernel(const int*   __restrict__ mask,
            const int*   __restrict__ psg_ids,
            const float* __restrict__ W,
            float*       __restrict__ out)
{
    const int l   = blockIdx.x;
    const int b   = blockIdx.y;
    const int tid = threadIdx.x;
    const long tok = (long)b * LEN + l;

    __shared__ int s_row;
    __shared__ int s_len;

    // reset work counter for the next launch (stream-ordered after argmax)
    if (l == 0 && b == 0 && tid == 0) g_counter = 0u;

    const int m = mask[tok];
    if (m != 0) {
        if (tid == 0) {
            unsigned long long best = 0ull;
            #pragma unroll
            for (int c = 0; c < CH; c++) {
                unsigned long long v = g_best[tok * CH + c];
                if (v > best) best = v;
            }
            int hot = (int)(0xFFFFFFFFu - (unsigned int)(best & 0xFFFFFFFFull));
            s_row = row_from_hot(hot);
        }
    } else {
        if (tid < LEN) {
            int mv = mask[(long)b * LEN + tid];
            int mp = (tid == 0) ? 1 : mask[(long)b * LEN + tid - 1];
            if (mv == 0 && mp != 0) s_len = tid;   // first zero == row length s
        }
        __syncthreads();
        if (tid == 0) {
            int s = s_len;
            s_row = (l == s) ? 1 : psg_ids[(long)b * LEN + (l - s - 1)];
        }
    }
    __syncthreads();

    const int row = s_row;
    const float4* src = reinterpret_cast<const float4*>(W) + (long)row * E4;
    float4*       dst = reinterpret_cast<float4*>(out) + tok * E4;
    if (tid < E4) dst[tid] = src[tid];
}

extern "C" void kernel_launch(void* const* d_in, const int* in_sizes, int n_in,
                              void* d_out, int out_size)
{
    const float* logits  = (const float*)d_in[0];
    const int*   mask    = (const int*)  d_in[1];
    const int*   psg_ids = (const int*)  d_in[2];
    const float* W       = (const float*)d_in[3];
    const float* gumbel  = (const float*)d_in[4];
    float*       out     = (float*)d_out;

    argmax_kernel<<<AGRID, ABLK>>>(logits, mask, gumbel);
    dim3 eg(LEN, BATCH);
    emit_kernel<<<eg, 192>>>(mask, psg_ids, W, out);
}

// round 3
// speedup vs baseline: 1.0440x; 1.0440x over previous
#include <cuda_runtime.h>
#include <math_constants.h>

#define BATCH 16
#define LEN   128
#define VOCAB 32128
#define EMB   768
#define V4    (VOCAB / 4)     // 8032
#define E4    (EMB / 4)       // 192
#define NTOK  (BATCH * LEN)   // 2048
#define SPLIT 4               // blocks per token
#define CHUNK_V4 (V4 / SPLIT) // 2008 float4-pairs (64KB) per block
#define TBLK  256
#define TNW   (TBLK / 32)     // 8

// Persistent scratch. Zero-initialized at module load; each launch leaves it
// zeroed again (last-arriving block resets its token), so graph replays are
// deterministic.
__device__ unsigned long long g_tokbest[NTOK];
__device__ unsigned int       g_arrive[NTOK];

// Bit-exact replication of XLA f32:
//   linspace(-1,1,V)[h] = -1 + h*fl(2/(V-1));  ix = ((c+1)*V - 1)/2
//   round half-even, clip. Discrete IEEE ops (no FMA contraction).
__device__ __forceinline__ int row_from_hot(int h) {
    const float delta = 2.0f / 32127.0f;
    float coord = __fadd_rn(-1.0f, __fmul_rn((float)h, delta));
    float t = __fadd_rn(coord, 1.0f);
    t = __fmul_rn(t, 32128.0f);
    t = __fsub_rn(t, 1.0f);
    t = __fdiv_rn(t, 2.0f);
    float r = rintf(t);
    r = fminf(fmaxf(r, 0.0f), 32127.0f);
    return (int)r;
}

// monotone f32 -> u32 key (total order preserved)
__device__ __forceinline__ unsigned int fkey(float v) {
    unsigned int b = __float_as_uint(v);
    unsigned int m = (unsigned int)((int)b >> 31) | 0x80000000u;
    return b ^ m;
}

__global__ void __launch_bounds__(TBLK)
fused_kernel(const float* __restrict__ logits,
             const int*   __restrict__ mask,
             const int*   __restrict__ psg_ids,
             const float* __restrict__ W,
             const float* __restrict__ gumbel,
             float*       __restrict__ out)
{
    const int item = blockIdx.x;
    const int tok  = item >> 2;          // SPLIT == 4
    const int c    = item & (SPLIT - 1);
    const int b    = tok >> 7;           // LEN == 128
    const int l    = tok & (LEN - 1);
    const int tid  = threadIdx.x;
    const int lane = tid & 31;
    const int wid  = tid >> 5;

    __shared__ float s_wv[TNW];
    __shared__ int   s_wi[TNW];
    __shared__ int   s_row;
    __shared__ int   s_len;
    __shared__ int   s_last;

    const int m = mask[tok];

    if (m != 0) {
        // ---- block argmax over this quarter of logits[tok,:] + gumbel[tok,:] ----
        const float4* lg = reinterpret_cast<const float4*>(logits) + (long)tok * V4;
        const float4* gn = reinterpret_cast<const float4*>(gumbel) + (long)tok * V4;
        const int i0  = c * CHUNK_V4;
        const int end = i0 + CHUNK_V4;

        float best = -CUDART_INF_F;
        int   bi   = 0x7fffffff;
        #pragma unroll 4
        for (int i = i0 + tid; i < end; i += TBLK) {
            float4 a = __ldg(lg + i);
            float4 g = __ldg(gn + i);
            float z0 = a.x + g.x, z1 = a.y + g.y, z2 = a.z + g.z, z3 = a.w + g.w;
            int base = i << 2;
            if (z0 > best) { best = z0; bi = base;     }
            if (z1 > best) { best = z1; bi = base + 1; }
            if (z2 > best) { best = z2; bi = base + 2; }
            if (z3 > best) { best = z3; bi = base + 3; }
        }
        // warp reduce: larger value wins; tie -> lower index
        #pragma unroll
        for (int off = 16; off > 0; off >>= 1) {
            float ov = __shfl_down_sync(0xffffffffu, best, off);
            int   oi = __shfl_down_sync(0xffffffffu, bi,   off);
            if (ov > best || (ov == best && oi < bi)) { best = ov; bi = oi; }
        }
        if (lane == 0) { s_wv[wid] = best; s_wi[wid] = bi; }
        __syncthreads();
        if (tid == 0) {
            best = s_wv[0]; bi = s_wi[0];
            #pragma unroll
            for (int w = 1; w < TNW; w++) {
                float ov = s_wv[w]; int oi = s_wi[w];
                if (ov > best || (ov == best && oi < bi)) { best = ov; bi = oi; }
            }
            unsigned long long packed =
                ((unsigned long long)fkey(best) << 32) |
                (unsigned long long)(0xFFFFFFFFu - (unsigned int)bi);
            atomicMax(&g_tokbest[tok], packed);
            __threadfence();
            unsigned int prev = atomicAdd(&g_arrive[tok], 1u);
            s_last = (prev == SPLIT - 1);
            if (s_last) {
                unsigned long long tb = atomicAdd(&g_tokbest[tok], 0ull);
                int hot = (int)(0xFFFFFFFFu - (unsigned int)(tb & 0xFFFFFFFFull));
                s_row = row_from_hot(hot);
                g_tokbest[tok] = 0ull;   // reset for next graph replay
                g_arrive[tok]  = 0u;
            }
        }
        __syncthreads();
    } else {
        // ---- masked token: only the last-arriving block does the passage branch ----
        if (tid == 0) {
            unsigned int prev = atomicAdd(&g_arrive[tok], 1u);
            s_last = (prev == SPLIT - 1);
            if (s_last) g_arrive[tok] = 0u;
        }
        __syncthreads();
        if (s_last) {
            // s = number of leading ones in mask[b,:] == first zero position
            if (tid < LEN) {
                int mv = mask[(long)b * LEN + tid];
                int mp = (tid == 0) ? 1 : mask[(long)b * LEN + tid - 1];
                if (mv == 0 && mp != 0) s_len = tid;
            }
            __syncthreads();
            if (tid == 0) {
                int s = s_len;
                // l >= s here: l==s -> BOS(=1); l>s -> psg_input_ids[b, l-s-1]
                s_row = (l == s) ? 1 : psg_ids[(long)b * LEN + (l - s - 1)];
            }
            __syncthreads();
        }
    }

    // ---- last-arriving block writes out[tok,:] = W[row,:] (bitwise copy) ----
    if (s_last) {
        const int row = s_row;
        const float4* src = reinterpret_cast<const float4*>(W) + (long)row * E4;
        float4*       dst = reinterpret_cast<float4*>(out) + (long)tok * E4;
        if (tid < E4) dst[tid] = src[tid];
    }
}

extern "C" void kernel_launch(void* const* d_in, const int* in_sizes, int n_in,
                              void* d_out, int out_size)
{
    const float* logits  = (const float*)d_in[0];
    const int*   mask    = (const int*)  d_in[1];
    const int*   psg_ids = (const int*)  d_in[2];
    const float* W       = (const float*)d_in[3];
    const float* gumbel  = (const float*)d_in[4];
    float*       out     = (float*)d_out;

    fused_kernel<<<NTOK * SPLIT, TBLK>>>(logits, mask, psg_ids, W, gumbel, out);
}

// round 4
// speedup vs baseline: 1.2176x; 1.1663x over previous
#include <cuda_runtime.h>
#include <math_constants.h>

#define BATCH 16
#define LEN   128
#define VOCAB 32128
#define EMB   768
#define V4    (VOCAB / 4)   // 8032
#define E4    (EMB / 4)     // 192
#define THREADS 512
#define NW (THREADS / 32)   // 16

// Bit-exact replication of XLA f32:
//   linspace(-1,1,V)[h] = -1 + h*fl(2/(V-1));  ix = ((c+1)*V - 1)/2
//   round half-even, clip. Discrete IEEE ops (no FMA contraction).
__device__ __forceinline__ int row_from_hot(int h) {
    const float delta = 2.0f / 32127.0f;                 // compile-time, IEEE RN
    float coord = __fadd_rn(-1.0f, __fmul_rn((float)h, delta));
    float t = __fadd_rn(coord, 1.0f);
    t = __fmul_rn(t, 32128.0f);
    t = __fsub_rn(t, 1.0f);
    t = __fdiv_rn(t, 2.0f);
    float r = rintf(t);                                  // half-to-even == jnp.round
    r = fminf(fmaxf(r, 0.0f), 32127.0f);
    return (int)r;
}

__global__ void __launch_bounds__(THREADS, 4)
fused_kernel(const float* __restrict__ logits,
             const int*   __restrict__ mask,
             const int*   __restrict__ psg_ids,
             const float* __restrict__ W,
             const float* __restrict__ gumbel,
             float*       __restrict__ out)
{
    const int l   = blockIdx.x;
    const int b   = blockIdx.y;
    const int tid = threadIdx.x;
    const long tok = (long)b * LEN + l;

    __shared__ int   s_final_idx;
    __shared__ float s_wv[NW];
    __shared__ int   s_wi[NW];
    __shared__ int   s_len;

    const int m = mask[tok];   // block-uniform

    if (m != 0) {
        // ---- argmax over logits[b,l,:] + gumbel[b,l,:] (first-max tie-break) ----
        // Streaming loads: data is read exactly once -> evict-first, keep L2 clean.
        const float4* lg = reinterpret_cast<const float4*>(logits) + tok * V4;
        const float4* gn = reinterpret_cast<const float4*>(gumbel) + tok * V4;
        float best = -CUDART_INF_F;
        int   bi   = 0x7fffffff;
        #pragma unroll 4
        for (int i = tid; i < V4; i += THREADS) {
            float4 a = __ldcs(lg + i);
            float4 g = __ldcs(gn + i);
            float z0 = a.x + g.x, z1 = a.y + g.y, z2 = a.z + g.z, z3 = a.w + g.w;
            int base = i << 2;
            if (z0 > best) { best = z0; bi = base;     }
            if (z1 > best) { best = z1; bi = base + 1; }
            if (z2 > best) { best = z2; bi = base + 2; }
            if (z3 > best) { best = z3; bi = base + 3; }
        }
        // warp reduce (prefer larger value, then lower index)
        #pragma unroll
        for (int off = 16; off > 0; off >>= 1) {
            float ov = __shfl_down_sync(0xffffffffu, best, off);
            int   oi = __shfl_down_sync(0xffffffffu, bi,   off);
            if (ov > best || (ov == best && oi < bi)) { best = ov; bi = oi; }
        }
        const int wid = tid >> 5, lane = tid & 31;
        if (lane == 0) { s_wv[wid] = best; s_wi[wid] = bi; }
        __syncthreads();
        if (wid == 0) {
            best = (lane < NW) ? s_wv[lane] : -CUDART_INF_F;
            bi   = (lane < NW) ? s_wi[lane] : 0x7fffffff;
            #pragma unroll
            for (int off = 16; off > 0; off >>= 1) {
                float ov = __shfl_down_sync(0xffffffffu, best, off);
                int   oi = __shfl_down_sync(0xffffffffu, bi,   off);
                if (ov > best || (ov == best && oi < bi)) { best = ov; bi = oi; }
            }
            if (lane == 0) s_final_idx = row_from_hot(bi);
        }
    } else {
        // ---- masked-off token: need s = sum(mask[b,:]) = first zero position ----
        if (tid < LEN) {
            int mv = mask[(long)b * LEN + tid];
            int mp = (tid == 0) ? 1 : mask[(long)b * LEN + tid - 1];
            if (mv == 0 && mp != 0) s_len = tid;   // exists: mask[b,l]==0
        }
        __syncthreads();
        if (tid == 0) {
            int s = s_len;
            // l >= s here: l==s -> BOS(=1); l>s -> psg_input_ids[b, l-s-1]
            s_final_idx = (l == s) ? 1 : psg_ids[(long)b * LEN + (l - s - 1)];
        }
    }
    __syncthreads();

    // ---- out[b,l,:] = W[row,:] (bitwise copy) ----
    const int row = s_final_idx;
    const float4* src = reinterpret_cast<const float4*>(W) + (long)row * E4;
    float4*       dst = reinterpret_cast<float4*>(out) + tok * E4;
    if (tid < E4) dst[tid] = src[tid];
}

extern "C" void kernel_launch(void* const* d_in, const int* in_sizes, int n_in,
                              void* d_out, int out_size)
{
    const float* logits  = (const float*)d_in[0];
    const int*   mask    = (const int*)  d_in[1];
    const int*   psg_ids = (const int*)  d_in[2];
    const float* W       = (const float*)d_in[3];
    const float* gumbel  = (const float*)d_in[4];
    float*       out     = (float*)d_out;

    dim3 grid(LEN, BATCH);
    fused_kernel<<<grid, THREADS>>>(logits, mask, psg_ids, W, gumbel, out);
}